// round 3
// baseline (speedup 1.0000x reference)
#include <cuda_runtime.h>
#include <math.h>

#define D        1024
#define E_TOT    10
#define E_TRUE   8
#define MAX_T    8192
#define BM       128
#define BN       128
#define BK       16

// Routing scratch (device globals: the sanctioned scratch space)
__device__ int   g_cnt[E_TRUE];
__device__ int   g_tok[E_TRUE * MAX_T];
__device__ float g_wt [E_TRUE * MAX_T];

// ---- packed f32x2 helpers (Blackwell; ptxas never emits these from C++) ----
__device__ __forceinline__ unsigned long long pack2(float a, float b) {
    unsigned long long r;
    asm("mov.b64 %0, {%1, %2};" : "=l"(r) : "f"(a), "f"(b));
    return r;
}
__device__ __forceinline__ void unpack2(unsigned long long v, float& a, float& b) {
    asm("mov.b64 {%0, %1}, %2;" : "=f"(a), "=f"(b) : "l"(v));
}
__device__ __forceinline__ void fma2(unsigned long long& d,
                                     unsigned long long a,
                                     unsigned long long b) {
    asm("fma.rn.f32x2 %0, %1, %2, %0;" : "+l"(d) : "l"(a), "l"(b));
}

// ---------------------------------------------------------------------------
__global__ void init_kernel() {
    if (threadIdx.x < E_TRUE) g_cnt[threadIdx.x] = 0;
}

// One warp per token: 10 dot products (len 1024), softmax, top-2, null-mask,
// renormalize, scatter into per-expert lists.
__global__ void gate_kernel(const float* __restrict__ x,
                            const float* __restrict__ gw,
                            const float* __restrict__ gb, int T) {
    int gtid = blockIdx.x * blockDim.x + threadIdx.x;
    int t = gtid >> 5;
    int lane = gtid & 31;
    if (t >= T) return;
    const float* xr = x + (size_t)t * D;

    float dot[E_TOT];
#pragma unroll
    for (int e = 0; e < E_TOT; e++) dot[e] = 0.f;

    for (int i = lane; i < D; i += 32) {
        float xv = xr[i];
#pragma unroll
        for (int e = 0; e < E_TOT; e++) dot[e] += xv * gw[e * D + i];
    }
#pragma unroll
    for (int e = 0; e < E_TOT; e++) {
#pragma unroll
        for (int off = 16; off; off >>= 1)
            dot[e] += __shfl_xor_sync(0xffffffffu, dot[e], off);
    }
    if (lane == 0) {
        float p[E_TOT];
        float mx = -1e30f;
#pragma unroll
        for (int e = 0; e < E_TOT; e++) {
            p[e] = dot[e] + gb[e];
            mx = fmaxf(mx, p[e]);
        }
        float s = 0.f;
#pragma unroll
        for (int e = 0; e < E_TOT; e++) { p[e] = expf(p[e] - mx); s += p[e]; }
        // top-2, lowest index wins ties (matches lax.top_k)
        int i1 = 0;
#pragma unroll
        for (int e = 1; e < E_TOT; e++) if (p[e] > p[i1]) i1 = e;
        int i2 = (i1 == 0) ? 1 : 0;
#pragma unroll
        for (int e = 0; e < E_TOT; e++)
            if (e != i1 && p[e] > p[i2]) i2 = e;

        float w1 = p[i1] / s, w2 = p[i2] / s;
        float t1 = (i1 < E_TRUE) ? w1 : 0.f;
        float t2 = (i2 < E_TRUE) ? w2 : 0.f;
        float den = t1 + t2;
        den = (den > 0.f) ? den : 1.f;
        t1 /= den;
        t2 /= den;
        if (i1 < E_TRUE) {
            int pos = atomicAdd(&g_cnt[i1], 1);
            g_tok[i1 * MAX_T + pos] = t;
            g_wt [i1 * MAX_T + pos] = t1;
        }
        if (i2 < E_TRUE) {
            int pos = atomicAdd(&g_cnt[i2], 1);
            g_tok[i2 * MAX_T + pos] = t;
            g_wt [i2 * MAX_T + pos] = t2;
        }
    }
}

// Grouped gather-GEMM: grid (N-tiles, M-tiles, experts). Double-buffered
// 128x128x16 tile, 8x8 per-thread micro-tile computed as 4 m-pairs x 8 n
// with packed fma.rn.f32x2. Epilogue: out[token] += w * (y + bias) via
// atomicAdd (<=2 adds/element -> commutative -> deterministic).
__global__ __launch_bounds__(256)
void moe_gemm(const float* __restrict__ x,
              const float* __restrict__ ew,
              const float* __restrict__ eb,
              float* __restrict__ out) {
    const int e = blockIdx.z;
    const int rows = g_cnt[e];
    const int m0 = blockIdx.y * BM;
    if (m0 >= rows) return;
    const int n0 = blockIdx.x * BN;

    __shared__ float As[2][BK][BM];
    __shared__ float Bs[2][BK][BN];
    __shared__ int   sTok[BM];
    __shared__ float sW[BM];

    const int tid = threadIdx.x;
    if (tid < BM) {
        int gr = m0 + tid;
        if (gr < rows) {
            sTok[tid] = g_tok[e * MAX_T + gr];
            sW[tid]   = g_wt [e * MAX_T + gr];
        } else {
            sTok[tid] = 0;   // valid address, result discarded in epilogue
            sW[tid]   = 0.f;
        }
    }
    __syncthreads();

    const float* wbase = ew + (size_t)e * D * D + n0;

    int aRow[2], aCol[2], bRow[2], bCol[2];
#pragma unroll
    for (int j = 0; j < 2; j++) {
        int idx = tid * 2 + j;          // 0..511
        aRow[j] = idx >> 2;  aCol[j] = idx & 3;   // 128 rows x 4 float4
        bRow[j] = idx >> 5;  bCol[j] = idx & 31;  // 16 rows  x 32 float4
    }
    float4 aReg[2], bReg[2];

    auto ldgAB = [&](int k0) {
#pragma unroll
        for (int j = 0; j < 2; j++) {
            aReg[j] = *(const float4*)(x + (size_t)sTok[aRow[j]] * D + k0 + aCol[j] * 4);
            bReg[j] = *(const float4*)(wbase + (size_t)(k0 + bRow[j]) * D + bCol[j] * 4);
        }
    };
    auto stsAB = [&](int buf) {
#pragma unroll
        for (int j = 0; j < 2; j++) {
            As[buf][aCol[j] * 4 + 0][aRow[j]] = aReg[j].x;
            As[buf][aCol[j] * 4 + 1][aRow[j]] = aReg[j].y;
            As[buf][aCol[j] * 4 + 2][aRow[j]] = aReg[j].z;
            As[buf][aCol[j] * 4 + 3][aRow[j]] = aReg[j].w;
            *(float4*)&Bs[buf][bRow[j]][bCol[j] * 4] = bReg[j];
        }
    };

    ldgAB(0);
    stsAB(0);
    __syncthreads();

    unsigned long long acc[4][8];
#pragma unroll
    for (int i = 0; i < 4; i++)
#pragma unroll
        for (int j = 0; j < 8; j++) acc[i][j] = 0ull;

    const int tmBase = (tid >> 4) * 8;
    const int tnBase = (tid & 15) * 8;
    const int NKB = D / BK;

    for (int kb = 0; kb < NKB; kb++) {
        const int buf = kb & 1;
        if (kb + 1 < NKB) ldgAB((kb + 1) * BK);
#pragma unroll
        for (int k = 0; k < BK; k++) {
            unsigned long long a2[4];
            const unsigned long long* ap =
                (const unsigned long long*)&As[buf][k][tmBase];
            a2[0] = ap[0]; a2[1] = ap[1]; a2[2] = ap[2]; a2[3] = ap[3];
            float bv[8];
            *(float4*)&bv[0] = *(const float4*)&Bs[buf][k][tnBase];
            *(float4*)&bv[4] = *(const float4*)&Bs[buf][k][tnBase + 4];
#pragma unroll
            for (int j = 0; j < 8; j++) {
                unsigned long long b2 = pack2(bv[j], bv[j]);
#pragma unroll
                for (int i = 0; i < 4; i++) fma2(acc[i][j], a2[i], b2);
            }
        }
        if (kb + 1 < NKB) stsAB(buf ^ 1);
        __syncthreads();
    }

    // Epilogue
    float bias[8];
#pragma unroll
    for (int j = 0; j < 8; j++) bias[j] = eb[e * D + n0 + tnBase + j];

#pragma unroll
    for (int i = 0; i < 4; i++) {
#pragma unroll
        for (int p = 0; p < 2; p++) {
            int ml = tmBase + 2 * i + p;
            int gr = m0 + ml;
            if (gr < rows) {
                int tok = sTok[ml];
                float w = sW[ml];
                float* orow = out + (size_t)tok * D + n0 + tnBase;
#pragma unroll
                for (int j = 0; j < 8; j++) {
                    float lo, hi;
                    unpack2(acc[i][j], lo, hi);
                    float y = p ? hi : lo;
                    atomicAdd(&orow[j], w * (y + bias[j]));
                }
            }
        }
    }
}

// ---------------------------------------------------------------------------
extern "C" void kernel_launch(void* const* d_in, const int* in_sizes, int n_in,
                              void* d_out, int out_size) {
    const float* x  = (const float*)d_in[0];
    const float* gw = (const float*)d_in[1];
    const float* gb = (const float*)d_in[2];
    const float* ew = (const float*)d_in[3];
    const float* eb = (const float*)d_in[4];
    float* out = (float*)d_out;

    const int T = in_sizes[0] / D;

    cudaMemsetAsync(out, 0, (size_t)out_size * sizeof(float), 0);
    init_kernel<<<1, 32>>>();

    int threads = 256;
    int blocks = (T * 32 + threads - 1) / threads;
    gate_kernel<<<blocks, threads>>>(x, gw, gb, T);

    dim3 grid(D / BN, (T + BM - 1) / BM, E_TRUE);
    moe_gemm<<<grid, 256>>>(x, ew, eb, out);
}

// round 4
// speedup vs baseline: 1.0024x; 1.0024x over previous
#include <cuda_runtime.h>
#include <math.h>

#define D        1024
#define E_TOT    10
#define E_TRUE   8
#define MAX_T    8192
#define BM       128
#define BN       128
#define BK       16

// Routing scratch (device globals: the sanctioned scratch space)
__device__ int   g_cnt[E_TRUE];
__device__ int   g_tok[E_TRUE * MAX_T];
__device__ float g_wt [E_TRUE * MAX_T];

// ---- packed f32x2 helpers (Blackwell; ptxas never emits these from C++) ----
__device__ __forceinline__ unsigned long long pack2(float a, float b) {
    unsigned long long r;
    asm("mov.b64 %0, {%1, %2};" : "=l"(r) : "f"(a), "f"(b));
    return r;
}
__device__ __forceinline__ void unpack2(unsigned long long v, float& a, float& b) {
    asm("mov.b64 {%0, %1}, %2;" : "=f"(a), "=f"(b) : "l"(v));
}
__device__ __forceinline__ void fma2(unsigned long long& d,
                                     unsigned long long a,
                                     unsigned long long b) {
    asm("fma.rn.f32x2 %0, %1, %2, %0;" : "+l"(d) : "l"(a), "l"(b));
}

// ---------------------------------------------------------------------------
__global__ void init_kernel() {
    if (threadIdx.x < E_TRUE) g_cnt[threadIdx.x] = 0;
}

// One warp per token: 10 dot products (len 1024), softmax, top-2, null-mask,
// renormalize, scatter into per-expert lists.
__global__ void gate_kernel(const float* __restrict__ x,
                            const float* __restrict__ gw,
                            const float* __restrict__ gb, int T) {
    int gtid = blockIdx.x * blockDim.x + threadIdx.x;
    int t = gtid >> 5;
    int lane = gtid & 31;
    if (t >= T) return;
    const float* xr = x + (size_t)t * D;

    float dot[E_TOT];
#pragma unroll
    for (int e = 0; e < E_TOT; e++) dot[e] = 0.f;

    for (int i = lane; i < D; i += 32) {
        float xv = xr[i];
#pragma unroll
        for (int e = 0; e < E_TOT; e++) dot[e] += xv * gw[e * D + i];
    }
#pragma unroll
    for (int e = 0; e < E_TOT; e++) {
#pragma unroll
        for (int off = 16; off; off >>= 1)
            dot[e] += __shfl_xor_sync(0xffffffffu, dot[e], off);
    }
    if (lane == 0) {
        float p[E_TOT];
        float mx = -1e30f;
#pragma unroll
        for (int e = 0; e < E_TOT; e++) {
            p[e] = dot[e] + gb[e];
            mx = fmaxf(mx, p[e]);
        }
        float s = 0.f;
#pragma unroll
        for (int e = 0; e < E_TOT; e++) { p[e] = expf(p[e] - mx); s += p[e]; }
        // top-2, lowest index wins ties (matches lax.top_k)
        int i1 = 0;
#pragma unroll
        for (int e = 1; e < E_TOT; e++) if (p[e] > p[i1]) i1 = e;
        int i2 = (i1 == 0) ? 1 : 0;
#pragma unroll
        for (int e = 0; e < E_TOT; e++)
            if (e != i1 && p[e] > p[i2]) i2 = e;

        float w1 = p[i1] / s, w2 = p[i2] / s;
        float t1 = (i1 < E_TRUE) ? w1 : 0.f;
        float t2 = (i2 < E_TRUE) ? w2 : 0.f;
        float den = t1 + t2;
        den = (den > 0.f) ? den : 1.f;
        t1 /= den;
        t2 /= den;
        if (i1 < E_TRUE) {
            int pos = atomicAdd(&g_cnt[i1], 1);
            g_tok[i1 * MAX_T + pos] = t;
            g_wt [i1 * MAX_T + pos] = t1;
        }
        if (i2 < E_TRUE) {
            int pos = atomicAdd(&g_cnt[i2], 1);
            g_tok[i2 * MAX_T + pos] = t;
            g_wt [i2 * MAX_T + pos] = t2;
        }
    }
}

// Grouped gather-GEMM: grid (N-tiles, M-tiles, experts). Double-buffered
// 128x128x16 tile, 8x8 per-thread micro-tile computed as 4 m-pairs x 8 n
// with packed fma.rn.f32x2. Epilogue: out[token] += w * (y + bias) via
// atomicAdd (<=2 adds/element -> commutative -> deterministic).
__global__ __launch_bounds__(256)
void moe_gemm(const float* __restrict__ x,
              const float* __restrict__ ew,
              const float* __restrict__ eb,
              float* __restrict__ out) {
    const int e = blockIdx.z;
    const int rows = g_cnt[e];
    const int m0 = blockIdx.y * BM;
    if (m0 >= rows) return;
    const int n0 = blockIdx.x * BN;

    __shared__ float As[2][BK][BM];
    __shared__ float Bs[2][BK][BN];
    __shared__ int   sTok[BM];
    __shared__ float sW[BM];

    const int tid = threadIdx.x;
    if (tid < BM) {
        int gr = m0 + tid;
        if (gr < rows) {
            sTok[tid] = g_tok[e * MAX_T + gr];
            sW[tid]   = g_wt [e * MAX_T + gr];
        } else {
            sTok[tid] = 0;   // valid address, result discarded in epilogue
            sW[tid]   = 0.f;
        }
    }
    __syncthreads();

    const float* wbase = ew + (size_t)e * D * D + n0;

    int aRow[2], aCol[2], bRow[2], bCol[2];
#pragma unroll
    for (int j = 0; j < 2; j++) {
        int idx = tid * 2 + j;          // 0..511
        aRow[j] = idx >> 2;  aCol[j] = idx & 3;   // 128 rows x 4 float4
        bRow[j] = idx >> 5;  bCol[j] = idx & 31;  // 16 rows  x 32 float4
    }
    float4 aReg[2], bReg[2];

    auto ldgAB = [&](int k0) {
#pragma unroll
        for (int j = 0; j < 2; j++) {
            aReg[j] = *(const float4*)(x + (size_t)sTok[aRow[j]] * D + k0 + aCol[j] * 4);
            bReg[j] = *(const float4*)(wbase + (size_t)(k0 + bRow[j]) * D + bCol[j] * 4);
        }
    };
    auto stsAB = [&](int buf) {
#pragma unroll
        for (int j = 0; j < 2; j++) {
            As[buf][aCol[j] * 4 + 0][aRow[j]] = aReg[j].x;
            As[buf][aCol[j] * 4 + 1][aRow[j]] = aReg[j].y;
            As[buf][aCol[j] * 4 + 2][aRow[j]] = aReg[j].z;
            As[buf][aCol[j] * 4 + 3][aRow[j]] = aReg[j].w;
            *(float4*)&Bs[buf][bRow[j]][bCol[j] * 4] = bReg[j];
        }
    };

    ldgAB(0);
    stsAB(0);
    __syncthreads();

    unsigned long long acc[4][8];
#pragma unroll
    for (int i = 0; i < 4; i++)
#pragma unroll
        for (int j = 0; j < 8; j++) acc[i][j] = 0ull;

    const int tmBase = (tid >> 4) * 8;
    const int tnBase = (tid & 15) * 8;
    const int NKB = D / BK;

    for (int kb = 0; kb < NKB; kb++) {
        const int buf = kb & 1;
        if (kb + 1 < NKB) ldgAB((kb + 1) * BK);
#pragma unroll
        for (int k = 0; k < BK; k++) {
            unsigned long long a2[4];
            const unsigned long long* ap =
                (const unsigned long long*)&As[buf][k][tmBase];
            a2[0] = ap[0]; a2[1] = ap[1]; a2[2] = ap[2]; a2[3] = ap[3];
            float bv[8];
            *(float4*)&bv[0] = *(const float4*)&Bs[buf][k][tnBase];
            *(float4*)&bv[4] = *(const float4*)&Bs[buf][k][tnBase + 4];
#pragma unroll
            for (int j = 0; j < 8; j++) {
                unsigned long long b2 = pack2(bv[j], bv[j]);
#pragma unroll
                for (int i = 0; i < 4; i++) fma2(acc[i][j], a2[i], b2);
            }
        }
        if (kb + 1 < NKB) stsAB(buf ^ 1);
        __syncthreads();
    }

    // Epilogue
    float bias[8];
#pragma unroll
    for (int j = 0; j < 8; j++) bias[j] = eb[e * D + n0 + tnBase + j];

#pragma unroll
    for (int i = 0; i < 4; i++) {
#pragma unroll
        for (int p = 0; p < 2; p++) {
            int ml = tmBase + 2 * i + p;
            int gr = m0 + ml;
            if (gr < rows) {
                int tok = sTok[ml];
                float w = sW[ml];
                float* orow = out + (size_t)tok * D + n0 + tnBase;
#pragma unroll
                for (int j = 0; j < 8; j++) {
                    float lo, hi;
                    unpack2(acc[i][j], lo, hi);
                    float y = p ? hi : lo;
                    atomicAdd(&orow[j], w * (y + bias[j]));
                }
            }
        }
    }
}

// ---------------------------------------------------------------------------
extern "C" void kernel_launch(void* const* d_in, const int* in_sizes, int n_in,
                              void* d_out, int out_size) {
    const float* x  = (const float*)d_in[0];
    const float* gw = (const float*)d_in[1];
    const float* gb = (const float*)d_in[2];
    const float* ew = (const float*)d_in[3];
    const float* eb = (const float*)d_in[4];
    float* out = (float*)d_out;

    const int T = in_sizes[0] / D;

    cudaMemsetAsync(out, 0, (size_t)out_size * sizeof(float), 0);
    init_kernel<<<1, 32>>>();

    int threads = 256;
    int blocks = (T * 32 + threads - 1) / threads;
    gate_kernel<<<blocks, threads>>>(x, gw, gb, T);

    dim3 grid(D / BN, (T + BM - 1) / BM, E_TRUE);
    moe_gemm<<<grid, 256>>>(x, ew, eb, out);
}